// round 2
// baseline (speedup 1.0000x reference)
#include <cuda_runtime.h>
#include <cuda_fp16.h>
#include <stdint.h>

// FeedForwardQuantum fused kernel:
//   q = cos(2*x[...,:8] + theta)                [rows, 8]
//   h = relu(q @ W1^T)                          [rows, 2048]
//   out = h @ W2^T                              [rows, 512]
// Fully fused: H tiles are materialized per-block in shared memory (fp16),
// big GEMM runs on tensor cores via mma.sync m16n8k16 (fp16 in, fp32 accum).

#define EMBED 512
#define FFN   2048
#define NQ    8

#define BM 128
#define BN 128
#define BK 64
#define HK 72            // padded smem stride (halves) -> conflict-free frags

__device__ __forceinline__ void mma16816(float* c,
                                         uint32_t a0, uint32_t a1, uint32_t a2, uint32_t a3,
                                         uint32_t b0, uint32_t b1) {
    asm volatile(
        "mma.sync.aligned.m16n8k16.row.col.f32.f16.f16.f32 "
        "{%0,%1,%2,%3}, {%4,%5,%6,%7}, {%8,%9}, {%0,%1,%2,%3};\n"
        : "+f"(c[0]), "+f"(c[1]), "+f"(c[2]), "+f"(c[3])
        : "r"(a0), "r"(a1), "r"(a2), "r"(a3), "r"(b0), "r"(b1));
}

__global__ __launch_bounds__(256, 2)
void ffq_fused_kernel(const float* __restrict__ x,
                      const float* __restrict__ theta,
                      const float* __restrict__ W1,
                      const float* __restrict__ W2,
                      float* __restrict__ out) {
    __shared__ float  qs[BM][NQ];        // 4 KB
    __shared__ float  w1s[NQ][BK];       // 2 KB (transposed chunk: [j][k])
    __shared__ __half Hs[BM][HK];        // 18 KB
    __shared__ __half W2s[BN][HK];       // 18 KB

    const int tid  = threadIdx.x;
    const int warp = tid >> 5;
    const int lane = tid & 31;
    const int g    = lane >> 2;          // 0..7
    const int t    = lane & 3;           // 0..3

    const int rowBase = blockIdx.x * BM;
    const int nBase   = blockIdx.y * BN;

    const int wm   = warp >> 2;          // 0..1
    const int wn   = warp & 3;           // 0..3
    const int moff = wm * 64;
    const int noff = wn * 32;

    // ---- q = cos(2*x + theta) for this block's rows ----
    float th[NQ];
    #pragma unroll
    for (int j = 0; j < NQ; ++j) th[j] = theta[j];

    #pragma unroll
    for (int i = 0; i < (BM * NQ) / 256; ++i) {
        int idx = tid + i * 256;
        int m = idx >> 3, j = idx & 7;
        float xv = x[(size_t)(rowBase + m) * EMBED + j];
        qs[m][j] = cosf(2.0f * xv + th[j]);
    }

    float acc[4][4][4];
    #pragma unroll
    for (int mi = 0; mi < 4; ++mi)
        #pragma unroll
        for (int ni = 0; ni < 4; ++ni)
            #pragma unroll
            for (int r = 0; r < 4; ++r) acc[mi][ni][r] = 0.0f;

    for (int kt = 0; kt < FFN / BK; ++kt) {
        __syncthreads();   // prev-iter consumers done; qs ready on first iter

        // ---- stage W1 chunk (transposed) + W2 chunk (fp32 -> fp16) ----
        {
            // W1 chunk rows [kt*64, kt*64+64) are 512 contiguous floats
            int idx = tid;
            #pragma unroll
            for (int i = 0; i < 2; ++i, idx += 256) {
                int k = idx >> 3, j = idx & 7;
                w1s[j][k] = W1[kt * (BK * NQ) + idx];
            }
        }
        {
            // W2 chunk: [BN rows] x [BK cols] -> 2048 float4 loads
            #pragma unroll
            for (int i = 0; i < 8; ++i) {
                int idx = tid + i * 256;
                int n = idx >> 4, c = idx & 15;
                float4 v = *(const float4*)&W2[(size_t)(nBase + n) * FFN + kt * BK + c * 4];
                __half2* dst = (__half2*)&W2s[n][c * 4];
                dst[0] = __floats2half2_rn(v.x, v.y);
                dst[1] = __floats2half2_rn(v.z, v.w);
            }
        }
        __syncthreads();

        // ---- compute H chunk: h[m][k] = relu(sum_j q[m][j]*W1[k][j]) ----
        #pragma unroll
        for (int i = 0; i < (BM * BK) / 256; ++i) {
            int idx = tid + i * 256;
            int m = idx >> 6, k = idx & 63;
            float h = 0.0f;
            #pragma unroll
            for (int j = 0; j < NQ; ++j) h += qs[m][j] * w1s[j][k];
            h = fmaxf(h, 0.0f);
            Hs[m][k] = __float2half_rn(h);
        }
        __syncthreads();

        // ---- tensor-core consume: 4 k16 steps ----
        #pragma unroll
        for (int ks = 0; ks < 4; ++ks) {
            uint32_t b[4][2];
            #pragma unroll
            for (int ni = 0; ni < 4; ++ni) {
                const __half* bb = &W2s[noff + ni * 8 + g][ks * 16 + 2 * t];
                b[ni][0] = *(const uint32_t*)bb;
                b[ni][1] = *(const uint32_t*)(bb + 8);
            }
            #pragma unroll
            for (int mi = 0; mi < 4; ++mi) {
                const __half* ab = &Hs[moff + mi * 16 + g][ks * 16 + 2 * t];
                uint32_t a0 = *(const uint32_t*)ab;
                uint32_t a1 = *(const uint32_t*)(ab + 8 * HK);
                uint32_t a2 = *(const uint32_t*)(ab + 8);
                uint32_t a3 = *(const uint32_t*)(ab + 8 * HK + 8);
                #pragma unroll
                for (int ni = 0; ni < 4; ++ni)
                    mma16816(acc[mi][ni], a0, a1, a2, a3, b[ni][0], b[ni][1]);
            }
        }
    }

    // ---- epilogue: fp32 stores ----
    #pragma unroll
    for (int mi = 0; mi < 4; ++mi) {
        int row = rowBase + moff + mi * 16 + g;
        #pragma unroll
        for (int ni = 0; ni < 4; ++ni) {
            int col = nBase + noff + ni * 8 + 2 * t;
            float2 v0 = make_float2(acc[mi][ni][0], acc[mi][ni][1]);
            float2 v1 = make_float2(acc[mi][ni][2], acc[mi][ni][3]);
            *(float2*)&out[(size_t)row * EMBED + col]       = v0;
            *(float2*)&out[(size_t)(row + 8) * EMBED + col] = v1;
        }
    }
}

extern "C" void kernel_launch(void* const* d_in, const int* in_sizes, int n_in,
                              void* d_out, int out_size) {
    const float* x     = (const float*)d_in[0];
    const float* theta = (const float*)d_in[1];
    const float* W1    = (const float*)d_in[2];
    const float* W2    = (const float*)d_in[3];
    float* out = (float*)d_out;

    int rows = in_sizes[0] / EMBED;      // 32768
    dim3 grid(rows / BM, EMBED / BN);    // (256, 4)
    ffq_fused_kernel<<<grid, 256>>>(x, theta, W1, W2, out);
}